// round 3
// baseline (speedup 1.0000x reference)
#include <cuda_runtime.h>

// Problem constants (fixed shapes per reference)
#define NN   50000
#define NE   1600000
#define FH   64
#define MH   512
#define DTC  0.1f
#define BDT  0.05f
#define KTE  14          // truncated Taylor depth (worst-mode tail ~1e-5; ref uses 40)
#define EPSF 1e-5f

// persistent Taylor kernel shape: must be co-resident for the software barrier
#define PBLK  592        // 148 SMs x 4 blocks (GB300 has 152 SMs -> fits)
#define PTHR  256
#define PWARPS (PBLK * (PTHR / 32))

// ---- scratch (no allocations allowed) ----
__device__ int      g_rowptr[NN + 1];
__device__ int      g_wptr[NN];
__device__ int      g_hcnt[NN];
__device__ int2     g_edge[NE];        // packed (col, __float_as_int(w))
__device__ float    g_ta[NN];
__device__ float    g_tb[NN];
__device__ float    g_P[NN];
__device__ float    g_unu[3 * NN];
__device__ float    g_hat[NN];
__device__ float    g_acc1[MH];
__device__ float    g_hm[MH];
__device__ unsigned g_bar;             // monotone grid-barrier counter (reset each launch)

__device__ __forceinline__ float wredall(float v) {
#pragma unroll
    for (int o = 16; o; o >>= 1) v += __shfl_xor_sync(0xffffffffu, v, o);
    return v;
}

// ---------------- init: zero counters, seed Taylor state ----------------
__global__ void k_init(const float* __restrict__ tau) {
    int i = blockIdx.x * blockDim.x + threadIdx.x;
    if (i < NN) {
        g_hcnt[i] = 0;
        float t = tau[i];
        g_ta[i] = t;   // term_0 = u0
        g_P[i]  = t;   // acc    = u0
    }
    if (i < MH) g_acc1[i] = 0.f;
    if (i == 0) g_bar = 0u;
}

// ---------------- CSR build: histogram ----------------
__global__ void k_hist(const int* __restrict__ eidx) {
    int e = blockIdx.x * blockDim.x + threadIdx.x;
    if (e >= NE) return;
    atomicAdd(&g_hcnt[eidx[e]], 1);
}

// single-block two-level (warp shuffle) prefix sum over 50000 counts
__global__ void k_scan() {
    __shared__ int s_ws[32];
    __shared__ int s_carry;
    int lane = threadIdx.x & 31, wid = threadIdx.x >> 5;
    if (threadIdx.x == 0) s_carry = 0;
    __syncthreads();
    for (int base = 0; base < NN; base += 1024) {
        int i = base + threadIdx.x;
        int v = (i < NN) ? g_hcnt[i] : 0;
        int x = v;
#pragma unroll
        for (int off = 1; off < 32; off <<= 1) {
            int t = __shfl_up_sync(0xffffffffu, x, off);
            if (lane >= off) x += t;
        }
        if (lane == 31) s_ws[wid] = x;
        __syncthreads();
        if (wid == 0) {
            int y = s_ws[lane];
#pragma unroll
            for (int off = 1; off < 32; off <<= 1) {
                int t = __shfl_up_sync(0xffffffffu, y, off);
                if (lane >= off) y += t;
            }
            s_ws[lane] = y;   // inclusive warp-sum scan
        }
        __syncthreads();
        int wbase = (wid == 0) ? 0 : s_ws[wid - 1];
        int excl  = s_carry + wbase + x - v;
        if (i < NN) { g_rowptr[i] = excl; g_wptr[i] = excl; }
        __syncthreads();
        if (threadIdx.x == 0) s_carry += s_ws[31];
        __syncthreads();
    }
    if (threadIdx.x == 0) g_rowptr[NN] = s_carry;
}

__global__ void k_scatter(const int* __restrict__ eidx, const float* __restrict__ ew) {
    int e = blockIdx.x * blockDim.x + threadIdx.x;
    if (e >= NE) return;
    int r = eidx[e];
    int p = atomicAdd(&g_wptr[r], 1);
    g_edge[p] = make_int2(eidx[NE + e], __float_as_int(ew[e]));  // one 8B store
}

// ---------------- fused Taylor loop: ONE persistent kernel, KTE iterations ----
// warp-per-row, grid-strided; software grid barrier between iterations.
// __threadfence() (gpu scope) emits CCTL.IVALL -> L1D invalidated, so plain
// loads of the ping-pong buffer after the barrier are coherent.
__global__ void __launch_bounds__(PTHR, 4) k_taylor() {
    int gw   = (blockIdx.x * PTHR + threadIdx.x) >> 5;
    int lane = threadIdx.x & 31;
    float* xin  = g_ta;
    float* xout = g_tb;
    for (int k = 1; k <= KTE; k++) {
        float coef = -BDT / (float)k;
        for (int node = gw; node < NN; node += PWARPS) {
            int s = g_rowptr[node], e = g_rowptr[node + 1];
            float sum = 0.f, sw = 0.f;
            for (int p = s + lane; p < e; p += 32) {
                int2 ed = g_edge[p];
                float w = __int_as_float(ed.y);
                sum = fmaf(w, xin[ed.x], sum);
                sw += w;
            }
            sum = wredall(sum);
            sw  = wredall(sw);
            if (lane == 0) {
                float t = coef * (sw * xin[node] - sum);
                xout[node] = t;
                g_P[node] += t;
            }
        }
        if (k == KTE) break;              // kernel boundary provides final sync
        // ---- grid barrier ----
        __threadfence();                  // publish xout stores
        __syncthreads();
        if (threadIdx.x == 0) {
            atomicAdd(&g_bar, 1u);
            unsigned target = (unsigned)k * PBLK;
            while (*((volatile unsigned*)&g_bar) < target) __nanosleep(64);
        }
        __syncthreads();
        __threadfence();                  // invalidate L1D before reading peer data
        float* t = xin; xin = xout; xout = t;
    }
}

// ---------------- per-node feature MLP (3 -> 64 -> 64 -> 3), warp per node ----------------
__global__ void k_mlp(const float* __restrict__ tau,
                      const float* __restrict__ gamma_p, const float* __restrict__ lam_p,
                      const float* __restrict__ fw1, const float* __restrict__ fb1,
                      const float* __restrict__ fg1, const float* __restrict__ fbt1,
                      const float* __restrict__ fw2, const float* __restrict__ fb2,
                      const float* __restrict__ fg2, const float* __restrict__ fbt2,
                      const float* __restrict__ fwo, const float* __restrict__ fbo) {
    __shared__ float s_fw1[3 * FH], s_fb1[FH], s_fg1[FH], s_fbt1[FH];
    __shared__ float s_fw2[FH * FH], s_fb2[FH], s_fg2[FH], s_fbt2[FH];
    __shared__ float s_fwo[FH * 3], s_fbo[3];
    int tid = threadIdx.x;
    for (int i = tid; i < 3 * FH; i += blockDim.x) s_fw1[i] = fw1[i];
    for (int i = tid; i < FH; i += blockDim.x) {
        s_fb1[i] = fb1[i]; s_fg1[i] = fg1[i]; s_fbt1[i] = fbt1[i];
        s_fb2[i] = fb2[i]; s_fg2[i] = fg2[i]; s_fbt2[i] = fbt2[i];
    }
    for (int i = tid; i < FH * FH; i += blockDim.x) s_fw2[i] = fw2[i];
    for (int i = tid; i < FH * 3; i += blockDim.x) s_fwo[i] = fwo[i];
    if (tid < 3) s_fbo[tid] = fbo[tid];
    __syncthreads();

    float gam = __ldg(gamma_p), lam = __ldg(lam_p);
    int node = (blockIdx.x * blockDim.x + tid) >> 5;   // exactly NN warps launched
    int lane = tid & 31;

    float tau_i = tau[node];
    float f0 = gam * tau_i;
    float f1 = lam * g_P[node];                        // f2 = mu*Q = 0
    int j0 = lane, j1 = lane + 32;

    // layer 1
    float ha = fmaf(f0, s_fw1[j0], fmaf(f1, s_fw1[FH + j0], s_fb1[j0]));
    float hb = fmaf(f0, s_fw1[j1], fmaf(f1, s_fw1[FH + j1], s_fb1[j1]));
    float m  = wredall(ha + hb) * (1.f / FH);
    float da = ha - m, db = hb - m;
    float var = wredall(da * da + db * db) * (1.f / FH);
    float rs  = rsqrtf(var + EPSF);
    ha = fmaxf(fmaf(da * rs, s_fg1[j0], s_fbt1[j0]), 0.f);
    hb = fmaxf(fmaf(db * rs, s_fg1[j1], s_fbt1[j1]), 0.f);

    // layer 2
    float aa = s_fb2[j0], ab = s_fb2[j1];
#pragma unroll
    for (int k = 0; k < 32; k++) {
        float hk = __shfl_sync(0xffffffffu, ha, k);
        aa = fmaf(hk, s_fw2[k * FH + j0], aa);
        ab = fmaf(hk, s_fw2[k * FH + j1], ab);
    }
#pragma unroll
    for (int k = 0; k < 32; k++) {
        float hk = __shfl_sync(0xffffffffu, hb, k);
        aa = fmaf(hk, s_fw2[(k + 32) * FH + j0], aa);
        ab = fmaf(hk, s_fw2[(k + 32) * FH + j1], ab);
    }
    m   = wredall(aa + ab) * (1.f / FH);
    da  = aa - m; db = ab - m;
    var = wredall(da * da + db * db) * (1.f / FH);
    rs  = rsqrtf(var + EPSF);
    aa = fmaxf(fmaf(da * rs, s_fg2[j0], s_fbt2[j0]), 0.f);
    ab = fmaxf(fmaf(db * rs, s_fg2[j1], s_fbt2[j1]), 0.f);

    // output layer (64 -> 3), reduce across warp
    float n0 = wredall(fmaf(aa, s_fwo[j0 * 3 + 0], ab * s_fwo[j1 * 3 + 0]));
    float n1 = wredall(fmaf(aa, s_fwo[j0 * 3 + 1], ab * s_fwo[j1 * 3 + 1]));
    float n2 = wredall(fmaf(aa, s_fwo[j0 * 3 + 2], ab * s_fwo[j1 * 3 + 2]));
    if (lane == 0) {
        g_unu[3 * node + 0] = tau_i * (n0 + s_fbo[0]);
        g_unu[3 * node + 1] = tau_i * (n1 + s_fbo[1]);
        g_unu[3 * node + 2] = tau_i * (n2 + s_fbo[2]);
    }
}

// ---------------- flux divergence + hat_u, warp per node ----------------
__global__ void k_flux(const float* __restrict__ tau) {
    int gt   = blockIdx.x * blockDim.x + threadIdx.x;
    int node = gt >> 5;
    int lane = gt & 31;
    int s = g_rowptr[node], e = g_rowptr[node + 1];
    float s0 = 0.f, s1 = 0.f, s2 = 0.f, sw = 0.f;
    for (int p = s + lane; p < e; p += 32) {
        int2 ed = g_edge[p];
        float w = __int_as_float(ed.y);
        int   c = ed.x;
        s0 = fmaf(w, __ldg(&g_unu[3 * c + 0]), s0);
        s1 = fmaf(w, __ldg(&g_unu[3 * c + 1]), s1);
        s2 = fmaf(w, __ldg(&g_unu[3 * c + 2]), s2);
        sw += w;
    }
    s0 = wredall(s0); s1 = wredall(s1); s2 = wredall(s2); sw = wredall(sw);
    if (lane == 0) {
        float d0 = sw * g_unu[3 * node + 0] - s0;
        float d1 = sw * g_unu[3 * node + 1] - s1;
        float d2 = sw * g_unu[3 * node + 2] - s2;
        float ds = sqrtf(d0 * d0 + d1 * d1 + d2 * d2 + 1e-12f);
        g_hat[node] = tau[node] + DTC * (g_P[node] - ds);   // Q = 0
    }
}

// ---------------- GEMV1: acc1[j] = sum over 2N useful rows of v[i]*mw1[i][j] ----------------
#define G1_ROWS 256
__global__ void k_gemv1(const float* __restrict__ mw1) {
    int tid = threadIdx.x;                 // 512 threads = MH columns
    int r0  = blockIdx.x * G1_ROWS;
    int r1  = min(r0 + G1_ROWS, 2 * NN);   // Q block (rows [2N,3N)) is zero: skipped
    float a0 = 0.f, a1 = 0.f, a2 = 0.f, a3 = 0.f;
    int r = r0;
    for (; r + 4 <= r1; r += 4) {
        float v0 = (r + 0 < NN) ? __ldg(&g_hat[r + 0]) : __ldg(&g_P[r + 0 - NN]);
        float v1 = (r + 1 < NN) ? __ldg(&g_hat[r + 1]) : __ldg(&g_P[r + 1 - NN]);
        float v2 = (r + 2 < NN) ? __ldg(&g_hat[r + 2]) : __ldg(&g_P[r + 2 - NN]);
        float v3 = (r + 3 < NN) ? __ldg(&g_hat[r + 3]) : __ldg(&g_P[r + 3 - NN]);
        a0 = fmaf(v0, __ldg(&mw1[(size_t)(r + 0) * MH + tid]), a0);
        a1 = fmaf(v1, __ldg(&mw1[(size_t)(r + 1) * MH + tid]), a1);
        a2 = fmaf(v2, __ldg(&mw1[(size_t)(r + 2) * MH + tid]), a2);
        a3 = fmaf(v3, __ldg(&mw1[(size_t)(r + 3) * MH + tid]), a3);
    }
    for (; r < r1; r++) {
        float v = (r < NN) ? __ldg(&g_hat[r]) : __ldg(&g_P[r - NN]);
        a0 = fmaf(v, __ldg(&mw1[(size_t)r * MH + tid]), a0);
    }
    atomicAdd(&g_acc1[tid], a0 + a1 + a2 + a3);
}

// ---------------- LayerNorm(512) + relu -> hm ----------------
__global__ void k_ln(const float* __restrict__ mb1, const float* __restrict__ mg1,
                     const float* __restrict__ mbt1) {
    __shared__ float red[16];
    int tid = threadIdx.x;                 // 512
    float x = g_acc1[tid] + mb1[tid];
    float v = wredall(x);
    if ((tid & 31) == 0) red[tid >> 5] = v;
    __syncthreads();
    float m = 0.f;
#pragma unroll
    for (int i = 0; i < 16; i++) m += red[i];
    m *= (1.f / MH);
    __syncthreads();
    float d = x - m;
    float v2 = wredall(d * d);
    if ((tid & 31) == 0) red[tid >> 5] = v2;
    __syncthreads();
    float var = 0.f;
#pragma unroll
    for (int i = 0; i < 16; i++) var += red[i];
    var *= (1.f / MH);
    g_hm[tid] = fmaxf(fmaf(d * rsqrtf(var + EPSF), mg1[tid], mbt1[tid]), 0.f);
}

// ---------------- GEMV2: out[n] = sum_k hm[k]*mwo[k][n] + mbo[n] + tau[n] ----------------
__global__ void k_gemv2(const float* __restrict__ mwo, const float* __restrict__ mbo,
                        const float* __restrict__ tau, float* __restrict__ out) {
    __shared__ float s_hm[MH];
    int tid = threadIdx.x;
    for (int i = tid; i < MH; i += blockDim.x) s_hm[i] = g_hm[i];
    __syncthreads();
    int n = blockIdx.x * blockDim.x + tid;
    if (n >= NN) return;
    float a0 = mbo[n], a1 = 0.f, a2 = 0.f, a3 = 0.f;
#pragma unroll 8
    for (int k = 0; k < MH; k += 4) {
        a0 = fmaf(s_hm[k + 0], __ldg(&mwo[(size_t)(k + 0) * NN + n]), a0);
        a1 = fmaf(s_hm[k + 1], __ldg(&mwo[(size_t)(k + 1) * NN + n]), a1);
        a2 = fmaf(s_hm[k + 2], __ldg(&mwo[(size_t)(k + 2) * NN + n]), a2);
        a3 = fmaf(s_hm[k + 3], __ldg(&mwo[(size_t)(k + 3) * NN + n]), a3);
    }
    out[n] = a0 + a1 + a2 + a3 + tau[n];
}

// ---------------- host orchestration ----------------
extern "C" void kernel_launch(void* const* d_in, const int* in_sizes, int n_in,
                              void* d_out, int out_size) {
    const float* tau   = (const float*)d_in[0];
    const int*   eidx  = (const int*)d_in[2];
    const float* ew    = (const float*)d_in[3];
    const float* gamma = (const float*)d_in[4];
    const float* lam   = (const float*)d_in[5];
    const float* fw1   = (const float*)d_in[7];
    const float* fb1   = (const float*)d_in[8];
    const float* fg1   = (const float*)d_in[9];
    const float* fbt1  = (const float*)d_in[10];
    const float* fw2   = (const float*)d_in[11];
    const float* fb2   = (const float*)d_in[12];
    const float* fg2   = (const float*)d_in[13];
    const float* fbt2  = (const float*)d_in[14];
    const float* fwo   = (const float*)d_in[15];
    const float* fbo   = (const float*)d_in[16];
    const float* mw1   = (const float*)d_in[17];
    const float* mb1   = (const float*)d_in[18];
    const float* mg1   = (const float*)d_in[19];
    const float* mbt1  = (const float*)d_in[20];
    const float* mwo   = (const float*)d_in[21];
    const float* mbo   = (const float*)d_in[22];
    float* out = (float*)d_out;

    // init + CSR build
    k_init<<<(NN + 255) / 256, 256>>>(tau);
    k_hist<<<(NE + 255) / 256, 256>>>(eidx);
    k_scan<<<1, 1024>>>();
    k_scatter<<<(NE + 255) / 256, 256>>>(eidx, ew);

    // fused Taylor loop: one persistent kernel, KTE iterations with grid barrier
    k_taylor<<<PBLK, PTHR>>>();

    // node MLP -> u_nu ; flux/div -> hat_u  (warp per node: NN warps)
    const int wpb = 256 / 32;
    const int node_blocks = NN / wpb;            // 6250
    k_mlp<<<node_blocks, 256>>>(tau, gamma, lam, fw1, fb1, fg1, fbt1,
                                fw2, fb2, fg2, fbt2, fwo, fbo);
    k_flux<<<node_blocks, 256>>>(tau);

    // big GEMVs + LN
    k_gemv1<<<(2 * NN + G1_ROWS - 1) / G1_ROWS, MH>>>(mw1);
    k_ln<<<1, MH>>>(mb1, mg1, mbt1);
    k_gemv2<<<(NN + 255) / 256, 256>>>(mwo, mbo, tau, out);
}

// round 4
// speedup vs baseline: 1.2026x; 1.2026x over previous
#include <cuda_runtime.h>

// Problem constants (fixed shapes per reference)
#define NN   50000
#define NE   1600000
#define FH   64
#define MH   512
#define DTC  0.1f
#define BDT  0.05f
#define KTE  14          // truncated Taylor depth (tail ~1e-5 worst mode; ref uses 40)
#define EPSF 1e-5f

// ---- scratch (no allocations allowed) ----
__device__ int   g_rowptr[NN + 1];
__device__ int   g_wptr[NN];
__device__ int   g_hcnt[NN];
__device__ int2  g_edge[NE];        // packed (col, __float_as_int(w))
__device__ float g_deg[NN];
__device__ float g_ta[NN];
__device__ float g_tb[NN];
__device__ float g_P[NN];
__device__ float g_unu[3 * NN];
__device__ float g_hat[NN];
__device__ float g_acc1[MH];
__device__ float g_hm[MH];

__device__ __forceinline__ float wredall(float v) {
#pragma unroll
    for (int o = 16; o; o >>= 1) v += __shfl_xor_sync(0xffffffffu, v, o);
    return v;
}

// ---------------- init ----------------
__global__ void k_init(const float* __restrict__ tau) {
    int i = blockIdx.x * blockDim.x + threadIdx.x;
    if (i < NN) {
        g_hcnt[i] = 0;
        g_deg[i]  = 0.f;
        float t = tau[i];
        g_ta[i] = t;   // term_0 = u0
        g_P[i]  = t;   // acc    = u0
    }
    if (i < MH) g_acc1[i] = 0.f;
}

// ---------------- CSR build: histogram + weighted degree ----------------
__global__ void k_hist(const int* __restrict__ eidx, const float* __restrict__ ew) {
    int e = blockIdx.x * blockDim.x + threadIdx.x;
    if (e >= NE) return;
    int r = eidx[e];
    atomicAdd(&g_hcnt[r], 1);
    atomicAdd(&g_deg[r], ew[e]);
}

// single-block two-level (warp shuffle) prefix sum over 50000 counts
__global__ void k_scan() {
    __shared__ int s_ws[32];
    __shared__ int s_carry;
    int lane = threadIdx.x & 31, wid = threadIdx.x >> 5;
    if (threadIdx.x == 0) s_carry = 0;
    __syncthreads();
    for (int base = 0; base < NN; base += 1024) {
        int i = base + threadIdx.x;
        int v = (i < NN) ? g_hcnt[i] : 0;
        int x = v;
#pragma unroll
        for (int off = 1; off < 32; off <<= 1) {
            int t = __shfl_up_sync(0xffffffffu, x, off);
            if (lane >= off) x += t;
        }
        if (lane == 31) s_ws[wid] = x;
        __syncthreads();
        if (wid == 0) {
            int y = s_ws[lane];
#pragma unroll
            for (int off = 1; off < 32; off <<= 1) {
                int t = __shfl_up_sync(0xffffffffu, y, off);
                if (lane >= off) y += t;
            }
            s_ws[lane] = y;   // inclusive warp-sum scan
        }
        __syncthreads();
        int wbase = (wid == 0) ? 0 : s_ws[wid - 1];
        int excl  = s_carry + wbase + x - v;
        if (i < NN) { g_rowptr[i] = excl; g_wptr[i] = excl; }
        __syncthreads();
        if (threadIdx.x == 0) s_carry += s_ws[31];
        __syncthreads();
    }
    if (threadIdx.x == 0) g_rowptr[NN] = s_carry;
}

__global__ void k_scatter(const int* __restrict__ eidx, const float* __restrict__ ew) {
    int e = blockIdx.x * blockDim.x + threadIdx.x;
    if (e >= NE) return;
    int r = eidx[e];
    int p = atomicAdd(&g_wptr[r], 1);
    g_edge[p] = make_int2(eidx[NE + e], __float_as_int(ew[e]));  // one 8B store
}

// ---------------- Taylor step: term = coef * L*term ; P += term ----------------
// warp per node; exactly NN warps per launch; deg precomputed
__global__ void k_spmv(const float* __restrict__ xin, float* __restrict__ xout, float coef) {
    int gt   = blockIdx.x * blockDim.x + threadIdx.x;
    int node = gt >> 5;
    int lane = gt & 31;
    int s = g_rowptr[node], e = g_rowptr[node + 1];
    float sum = 0.f;
    for (int p = s + lane; p < e; p += 32) {
        int2 ed = g_edge[p];
        sum = fmaf(__int_as_float(ed.y), __ldg(&xin[ed.x]), sum);
    }
    sum = wredall(sum);
    if (lane == 0) {
        float t = coef * (g_deg[node] * xin[node] - sum);
        xout[node] = t;
        g_P[node] += t;
    }
}

// ---------------- per-node feature MLP (3 -> 64 -> 64 -> 3) ----------------
// 1024-thread blocks (32 nodes each) to amortize the smem weight staging 4x
__global__ void __launch_bounds__(1024) k_mlp(
                      const float* __restrict__ tau,
                      const float* __restrict__ gamma_p, const float* __restrict__ lam_p,
                      const float* __restrict__ fw1, const float* __restrict__ fb1,
                      const float* __restrict__ fg1, const float* __restrict__ fbt1,
                      const float* __restrict__ fw2, const float* __restrict__ fb2,
                      const float* __restrict__ fg2, const float* __restrict__ fbt2,
                      const float* __restrict__ fwo, const float* __restrict__ fbo) {
    __shared__ float s_fw1[3 * FH], s_fb1[FH], s_fg1[FH], s_fbt1[FH];
    __shared__ float s_fw2[FH * FH], s_fb2[FH], s_fg2[FH], s_fbt2[FH];
    __shared__ float s_fwo[FH * 3], s_fbo[3];
    int tid = threadIdx.x;
    for (int i = tid; i < 3 * FH; i += blockDim.x) s_fw1[i] = fw1[i];
    if (tid < FH) {
        s_fb1[tid] = fb1[tid]; s_fg1[tid] = fg1[tid]; s_fbt1[tid] = fbt1[tid];
        s_fb2[tid] = fb2[tid]; s_fg2[tid] = fg2[tid]; s_fbt2[tid] = fbt2[tid];
    }
    for (int i = tid; i < FH * FH; i += blockDim.x) s_fw2[i] = fw2[i];
    for (int i = tid; i < FH * 3; i += blockDim.x) s_fwo[i] = fwo[i];
    if (tid < 3) s_fbo[tid] = fbo[tid];
    __syncthreads();

    int node = blockIdx.x * 32 + (tid >> 5);
    if (node >= NN) return;
    int lane = tid & 31;
    float gam = __ldg(gamma_p), lam = __ldg(lam_p);

    float tau_i = tau[node];
    float f0 = gam * tau_i;
    float f1 = lam * g_P[node];                        // f2 = mu*Q = 0
    int j0 = lane, j1 = lane + 32;

    // layer 1
    float ha = fmaf(f0, s_fw1[j0], fmaf(f1, s_fw1[FH + j0], s_fb1[j0]));
    float hb = fmaf(f0, s_fw1[j1], fmaf(f1, s_fw1[FH + j1], s_fb1[j1]));
    float m  = wredall(ha + hb) * (1.f / FH);
    float da = ha - m, db = hb - m;
    float var = wredall(da * da + db * db) * (1.f / FH);
    float rs  = rsqrtf(var + EPSF);
    ha = fmaxf(fmaf(da * rs, s_fg1[j0], s_fbt1[j0]), 0.f);
    hb = fmaxf(fmaf(db * rs, s_fg1[j1], s_fbt1[j1]), 0.f);

    // layer 2
    float aa = s_fb2[j0], ab = s_fb2[j1];
#pragma unroll
    for (int k = 0; k < 32; k++) {
        float hk = __shfl_sync(0xffffffffu, ha, k);
        aa = fmaf(hk, s_fw2[k * FH + j0], aa);
        ab = fmaf(hk, s_fw2[k * FH + j1], ab);
    }
#pragma unroll
    for (int k = 0; k < 32; k++) {
        float hk = __shfl_sync(0xffffffffu, hb, k);
        aa = fmaf(hk, s_fw2[(k + 32) * FH + j0], aa);
        ab = fmaf(hk, s_fw2[(k + 32) * FH + j1], ab);
    }
    m   = wredall(aa + ab) * (1.f / FH);
    da  = aa - m; db = ab - m;
    var = wredall(da * da + db * db) * (1.f / FH);
    rs  = rsqrtf(var + EPSF);
    aa = fmaxf(fmaf(da * rs, s_fg2[j0], s_fbt2[j0]), 0.f);
    ab = fmaxf(fmaf(db * rs, s_fg2[j1], s_fbt2[j1]), 0.f);

    // output layer (64 -> 3), reduce across warp
    float n0 = wredall(fmaf(aa, s_fwo[j0 * 3 + 0], ab * s_fwo[j1 * 3 + 0]));
    float n1 = wredall(fmaf(aa, s_fwo[j0 * 3 + 1], ab * s_fwo[j1 * 3 + 1]));
    float n2 = wredall(fmaf(aa, s_fwo[j0 * 3 + 2], ab * s_fwo[j1 * 3 + 2]));
    if (lane == 0) {
        g_unu[3 * node + 0] = tau_i * (n0 + s_fbo[0]);
        g_unu[3 * node + 1] = tau_i * (n1 + s_fbo[1]);
        g_unu[3 * node + 2] = tau_i * (n2 + s_fbo[2]);
    }
}

// ---------------- flux divergence + hat_u, warp per node ----------------
__global__ void k_flux(const float* __restrict__ tau) {
    int gt   = blockIdx.x * blockDim.x + threadIdx.x;
    int node = gt >> 5;
    int lane = gt & 31;
    int s = g_rowptr[node], e = g_rowptr[node + 1];
    float s0 = 0.f, s1 = 0.f, s2 = 0.f;
    for (int p = s + lane; p < e; p += 32) {
        int2 ed = g_edge[p];
        float w = __int_as_float(ed.y);
        int   c = ed.x;
        s0 = fmaf(w, __ldg(&g_unu[3 * c + 0]), s0);
        s1 = fmaf(w, __ldg(&g_unu[3 * c + 1]), s1);
        s2 = fmaf(w, __ldg(&g_unu[3 * c + 2]), s2);
    }
    s0 = wredall(s0); s1 = wredall(s1); s2 = wredall(s2);
    if (lane == 0) {
        float d  = g_deg[node];
        float d0 = d * g_unu[3 * node + 0] - s0;
        float d1 = d * g_unu[3 * node + 1] - s1;
        float d2 = d * g_unu[3 * node + 2] - s2;
        float ds = sqrtf(d0 * d0 + d1 * d1 + d2 * d2 + 1e-12f);
        g_hat[node] = tau[node] + DTC * (g_P[node] - ds);   // Q = 0
    }
}

// ---------------- GEMV1: acc1 += v[r]*mw1[r][:], float4 per thread ----------------
// 500 blocks x 128 threads; block handles 200 rows; thread owns cols 4c..4c+3.
// Q block (rows [2N,3N)) of mw1 is multiplied by zero in the reference: skipped.
#define G1_ROWS 200
__global__ void k_gemv1(const float* __restrict__ mw1) {
    int c  = threadIdx.x;                  // 0..127 -> float4 column group
    int r0 = blockIdx.x * G1_ROWS;         // NN % G1_ROWS == 0 -> no straddling
    const float* v = (r0 < NN) ? (g_hat + r0) : (g_P + (r0 - NN));
    const float4* m4 = (const float4*)mw1 + (size_t)r0 * (MH / 4) + c;
    float4 acc = make_float4(0.f, 0.f, 0.f, 0.f);
#pragma unroll 8
    for (int i = 0; i < G1_ROWS; i++) {
        float  vv = __ldg(&v[i]);
        float4 m  = __ldg(&m4[(size_t)i * (MH / 4)]);
        acc.x = fmaf(vv, m.x, acc.x);
        acc.y = fmaf(vv, m.y, acc.y);
        acc.z = fmaf(vv, m.z, acc.z);
        acc.w = fmaf(vv, m.w, acc.w);
    }
    atomicAdd(&g_acc1[4 * c + 0], acc.x);
    atomicAdd(&g_acc1[4 * c + 1], acc.y);
    atomicAdd(&g_acc1[4 * c + 2], acc.z);
    atomicAdd(&g_acc1[4 * c + 3], acc.w);
}

// ---------------- LayerNorm(512) + relu -> hm ----------------
__global__ void k_ln(const float* __restrict__ mb1, const float* __restrict__ mg1,
                     const float* __restrict__ mbt1) {
    __shared__ float red[16];
    int tid = threadIdx.x;                 // 512
    float x = g_acc1[tid] + mb1[tid];
    float v = wredall(x);
    if ((tid & 31) == 0) red[tid >> 5] = v;
    __syncthreads();
    float m = 0.f;
#pragma unroll
    for (int i = 0; i < 16; i++) m += red[i];
    m *= (1.f / MH);
    __syncthreads();
    float d = x - m;
    float v2 = wredall(d * d);
    if ((tid & 31) == 0) red[tid >> 5] = v2;
    __syncthreads();
    float var = 0.f;
#pragma unroll
    for (int i = 0; i < 16; i++) var += red[i];
    var *= (1.f / MH);
    g_hm[tid] = fmaxf(fmaf(d * rsqrtf(var + EPSF), mg1[tid], mbt1[tid]), 0.f);
}

// ---------------- out init: out[n] = mbo[n] + tau[n] ----------------
__global__ void k_outinit(const float* __restrict__ mbo, const float* __restrict__ tau,
                          float* __restrict__ out) {
    int n = blockIdx.x * blockDim.x + threadIdx.x;
    if (n < NN) out[n] = mbo[n] + tau[n];
}

// ---------------- GEMV2: out[4c..] += sum_k hm[k]*mwo[k][4c..], float4, 2D grid ----------------
#define G2_KC 128                         // k-chunk per block.y (4 chunks)
__global__ void k_gemv2(const float* __restrict__ mwo, float* __restrict__ out) {
    __shared__ float s_hm[G2_KC];
    int tid = threadIdx.x;                 // 128
    int kc  = blockIdx.y * G2_KC;
    s_hm[tid] = g_hm[kc + tid];
    __syncthreads();
    int c4 = blockIdx.x * 128 + tid;       // float4 column group, 12500 total
    if (c4 >= NN / 4) return;
    const float4* w4 = (const float4*)mwo + (size_t)kc * (NN / 4) + c4;
    float4 acc = make_float4(0.f, 0.f, 0.f, 0.f);
#pragma unroll 8
    for (int kk = 0; kk < G2_KC; kk++) {
        float  h = s_hm[kk];
        float4 m = __ldg(&w4[(size_t)kk * (NN / 4)]);
        acc.x = fmaf(h, m.x, acc.x);
        acc.y = fmaf(h, m.y, acc.y);
        acc.z = fmaf(h, m.z, acc.z);
        acc.w = fmaf(h, m.w, acc.w);
    }
    atomicAdd(&out[4 * c4 + 0], acc.x);
    atomicAdd(&out[4 * c4 + 1], acc.y);
    atomicAdd(&out[4 * c4 + 2], acc.z);
    atomicAdd(&out[4 * c4 + 3], acc.w);
}

// ---------------- host orchestration ----------------
extern "C" void kernel_launch(void* const* d_in, const int* in_sizes, int n_in,
                              void* d_out, int out_size) {
    const float* tau   = (const float*)d_in[0];
    const int*   eidx  = (const int*)d_in[2];
    const float* ew    = (const float*)d_in[3];
    const float* gamma = (const float*)d_in[4];
    const float* lam   = (const float*)d_in[5];
    const float* fw1   = (const float*)d_in[7];
    const float* fb1   = (const float*)d_in[8];
    const float* fg1   = (const float*)d_in[9];
    const float* fbt1  = (const float*)d_in[10];
    const float* fw2   = (const float*)d_in[11];
    const float* fb2   = (const float*)d_in[12];
    const float* fg2   = (const float*)d_in[13];
    const float* fbt2  = (const float*)d_in[14];
    const float* fwo   = (const float*)d_in[15];
    const float* fbo   = (const float*)d_in[16];
    const float* mw1   = (const float*)d_in[17];
    const float* mb1   = (const float*)d_in[18];
    const float* mg1   = (const float*)d_in[19];
    const float* mbt1  = (const float*)d_in[20];
    const float* mwo   = (const float*)d_in[21];
    const float* mbo   = (const float*)d_in[22];
    float* out = (float*)d_out;

    // init + CSR build (deg precomputed in hist)
    k_init<<<(NN + 255) / 256, 256>>>(tau);
    k_hist<<<(NE + 255) / 256, 256>>>(eidx, ew);
    k_scan<<<1, 1024>>>();
    k_scatter<<<(NE + 255) / 256, 256>>>(eidx, ew);

    // Taylor loop: separate launches (launch overhead measured negligible)
    float *pa = nullptr, *pb = nullptr;
    cudaGetSymbolAddress((void**)&pa, g_ta);
    cudaGetSymbolAddress((void**)&pb, g_tb);
    const int node_blocks = NN / 8;              // 6250 (warp per node, 256 thr)
    for (int k = 1; k <= KTE; k++) {
        float coef = -BDT / (float)k;
        k_spmv<<<node_blocks, 256>>>(pa, pb, coef);
        float* t = pa; pa = pb; pb = t;
    }

    // node MLP -> u_nu ; flux/div -> hat_u
    k_mlp<<<(NN + 31) / 32, 1024>>>(tau, gamma, lam, fw1, fb1, fg1, fbt1,
                                    fw2, fb2, fg2, fbt2, fwo, fbo);
    k_flux<<<node_blocks, 256>>>(tau);

    // big GEMVs + LN
    k_gemv1<<<(2 * NN) / G1_ROWS, 128>>>(mw1);   // 500 blocks
    k_ln<<<1, MH>>>(mb1, mg1, mbt1);
    k_outinit<<<(NN + 255) / 256, 256>>>(mbo, tau, out);
    {
        dim3 g((NN / 4 + 127) / 128, MH / G2_KC);  // (98, 4)
        k_gemv2<<<g, 128>>>(mwo, out);
    }
}

// round 5
// speedup vs baseline: 1.3151x; 1.0936x over previous
#include <cuda_runtime.h>

// Problem constants (fixed shapes per reference)
#define NN   50000
#define NE   1600000
#define FH   64
#define MH   512
#define DTC  0.1f
#define BDT  0.05f
#define KTE  12          // truncated Taylor depth (tail ~1e-7 rel; ref uses 40)
#define EPSF 1e-5f

// ---- scratch (no allocations allowed) ----
__device__ int   g_rowptr[NN + 1];
__device__ int   g_wptr[NN];
__device__ int   g_hcnt[NN];
__device__ int2  g_edge[NE];        // packed (col, __float_as_int(w))
__device__ float g_deg[NN];
__device__ float g_ta[NN];
__device__ float g_tb[NN];
__device__ float g_P[NN];
__device__ float g_unu[3 * NN];
__device__ float g_hat[NN];
__device__ float g_acc1[MH];
__device__ float g_hm[MH];

__device__ __forceinline__ float wredall(float v) {
#pragma unroll
    for (int o = 16; o; o >>= 1) v += __shfl_xor_sync(0xffffffffu, v, o);
    return v;
}
// reduce within 16-lane half-warp
__device__ __forceinline__ float hredall(float v) {
#pragma unroll
    for (int o = 8; o; o >>= 1) v += __shfl_xor_sync(0xffffffffu, v, o);
    return v;
}

// ---------------- init ----------------
__global__ void k_init(const float* __restrict__ tau) {
    int i = blockIdx.x * blockDim.x + threadIdx.x;
    if (i < NN) {
        g_hcnt[i] = 0;
        g_deg[i]  = 0.f;
        float t = tau[i];
        g_ta[i] = t;   // term_0 = u0
        g_P[i]  = t;   // acc    = u0
    }
    if (i < MH) g_acc1[i] = 0.f;
}

// ---------------- CSR build: histogram + weighted degree (4 edges/thread) ----
__global__ void k_hist(const int* __restrict__ eidx, const float* __restrict__ ew) {
    int e4 = blockIdx.x * blockDim.x + threadIdx.x;
    if (e4 >= NE / 4) return;
    int4   r = __ldg(((const int4*)eidx) + e4);
    float4 w = __ldg(((const float4*)ew) + e4);
    atomicAdd(&g_hcnt[r.x], 1); atomicAdd(&g_deg[r.x], w.x);
    atomicAdd(&g_hcnt[r.y], 1); atomicAdd(&g_deg[r.y], w.y);
    atomicAdd(&g_hcnt[r.z], 1); atomicAdd(&g_deg[r.z], w.z);
    atomicAdd(&g_hcnt[r.w], 1); atomicAdd(&g_deg[r.w], w.w);
}

// single-block two-level (warp shuffle) prefix sum over 50000 counts
__global__ void k_scan() {
    __shared__ int s_ws[32];
    __shared__ int s_carry;
    int lane = threadIdx.x & 31, wid = threadIdx.x >> 5;
    if (threadIdx.x == 0) s_carry = 0;
    __syncthreads();
    for (int base = 0; base < NN; base += 1024) {
        int i = base + threadIdx.x;
        int v = (i < NN) ? g_hcnt[i] : 0;
        int x = v;
#pragma unroll
        for (int off = 1; off < 32; off <<= 1) {
            int t = __shfl_up_sync(0xffffffffu, x, off);
            if (lane >= off) x += t;
        }
        if (lane == 31) s_ws[wid] = x;
        __syncthreads();
        if (wid == 0) {
            int y = s_ws[lane];
#pragma unroll
            for (int off = 1; off < 32; off <<= 1) {
                int t = __shfl_up_sync(0xffffffffu, y, off);
                if (lane >= off) y += t;
            }
            s_ws[lane] = y;   // inclusive warp-sum scan
        }
        __syncthreads();
        int wbase = (wid == 0) ? 0 : s_ws[wid - 1];
        int excl  = s_carry + wbase + x - v;
        if (i < NN) { g_rowptr[i] = excl; g_wptr[i] = excl; }
        __syncthreads();
        if (threadIdx.x == 0) s_carry += s_ws[31];
        __syncthreads();
    }
    if (threadIdx.x == 0) g_rowptr[NN] = s_carry;
}

// 4 edges per thread
__global__ void k_scatter(const int* __restrict__ eidx, const float* __restrict__ ew) {
    int e4 = blockIdx.x * blockDim.x + threadIdx.x;
    if (e4 >= NE / 4) return;
    int4   r = __ldg(((const int4*)eidx) + e4);
    int4   c = __ldg(((const int4*)(eidx + NE)) + e4);
    float4 w = __ldg(((const float4*)ew) + e4);
    int p;
    p = atomicAdd(&g_wptr[r.x], 1); g_edge[p] = make_int2(c.x, __float_as_int(w.x));
    p = atomicAdd(&g_wptr[r.y], 1); g_edge[p] = make_int2(c.y, __float_as_int(w.y));
    p = atomicAdd(&g_wptr[r.z], 1); g_edge[p] = make_int2(c.z, __float_as_int(w.z));
    p = atomicAdd(&g_wptr[r.w], 1); g_edge[p] = make_int2(c.w, __float_as_int(w.w));
}

// ---------------- Taylor step: term = coef * L*term ; P += term ----------------
// TWO nodes per warp (16 lanes each); NN/2 warps per launch (NN even)
__global__ void k_spmv(const float* __restrict__ xin, float* __restrict__ xout, float coef) {
    int gt     = blockIdx.x * blockDim.x + threadIdx.x;
    int node   = gt >> 4;            // 16 lanes per node
    int lane16 = gt & 15;
    int s = g_rowptr[node], e = g_rowptr[node + 1];
    float sum = 0.f;
    for (int p = s + lane16; p < e; p += 16) {
        int2 ed = g_edge[p];
        sum = fmaf(__int_as_float(ed.y), __ldg(&xin[ed.x]), sum);
    }
    sum = hredall(sum);
    if (lane16 == 0) {
        float t = coef * (g_deg[node] * xin[node] - sum);
        xout[node] = t;
        g_P[node] += t;
    }
}

// ---------------- per-node feature MLP (3 -> 64 -> 64 -> 3) ----------------
// 1024-thread blocks (32 nodes each) to amortize the smem weight staging 4x
__global__ void __launch_bounds__(1024) k_mlp(
                      const float* __restrict__ tau,
                      const float* __restrict__ gamma_p, const float* __restrict__ lam_p,
                      const float* __restrict__ fw1, const float* __restrict__ fb1,
                      const float* __restrict__ fg1, const float* __restrict__ fbt1,
                      const float* __restrict__ fw2, const float* __restrict__ fb2,
                      const float* __restrict__ fg2, const float* __restrict__ fbt2,
                      const float* __restrict__ fwo, const float* __restrict__ fbo) {
    __shared__ float s_fw1[3 * FH], s_fb1[FH], s_fg1[FH], s_fbt1[FH];
    __shared__ float s_fw2[FH * FH], s_fb2[FH], s_fg2[FH], s_fbt2[FH];
    __shared__ float s_fwo[FH * 3], s_fbo[3];
    int tid = threadIdx.x;
    for (int i = tid; i < 3 * FH; i += blockDim.x) s_fw1[i] = fw1[i];
    if (tid < FH) {
        s_fb1[tid] = fb1[tid]; s_fg1[tid] = fg1[tid]; s_fbt1[tid] = fbt1[tid];
        s_fb2[tid] = fb2[tid]; s_fg2[tid] = fg2[tid]; s_fbt2[tid] = fbt2[tid];
    }
    for (int i = tid; i < FH * FH; i += blockDim.x) s_fw2[i] = fw2[i];
    for (int i = tid; i < FH * 3; i += blockDim.x) s_fwo[i] = fwo[i];
    if (tid < 3) s_fbo[tid] = fbo[tid];
    __syncthreads();

    int node = blockIdx.x * 32 + (tid >> 5);
    if (node >= NN) return;
    int lane = tid & 31;
    float gam = __ldg(gamma_p), lam = __ldg(lam_p);

    float tau_i = tau[node];
    float f0 = gam * tau_i;
    float f1 = lam * g_P[node];                        // f2 = mu*Q = 0
    int j0 = lane, j1 = lane + 32;

    // layer 1
    float ha = fmaf(f0, s_fw1[j0], fmaf(f1, s_fw1[FH + j0], s_fb1[j0]));
    float hb = fmaf(f0, s_fw1[j1], fmaf(f1, s_fw1[FH + j1], s_fb1[j1]));
    float m  = wredall(ha + hb) * (1.f / FH);
    float da = ha - m, db = hb - m;
    float var = wredall(da * da + db * db) * (1.f / FH);
    float rs  = rsqrtf(var + EPSF);
    ha = fmaxf(fmaf(da * rs, s_fg1[j0], s_fbt1[j0]), 0.f);
    hb = fmaxf(fmaf(db * rs, s_fg1[j1], s_fbt1[j1]), 0.f);

    // layer 2
    float aa = s_fb2[j0], ab = s_fb2[j1];
#pragma unroll
    for (int k = 0; k < 32; k++) {
        float hk = __shfl_sync(0xffffffffu, ha, k);
        aa = fmaf(hk, s_fw2[k * FH + j0], aa);
        ab = fmaf(hk, s_fw2[k * FH + j1], ab);
    }
#pragma unroll
    for (int k = 0; k < 32; k++) {
        float hk = __shfl_sync(0xffffffffu, hb, k);
        aa = fmaf(hk, s_fw2[(k + 32) * FH + j0], aa);
        ab = fmaf(hk, s_fw2[(k + 32) * FH + j1], ab);
    }
    m   = wredall(aa + ab) * (1.f / FH);
    da  = aa - m; db = ab - m;
    var = wredall(da * da + db * db) * (1.f / FH);
    rs  = rsqrtf(var + EPSF);
    aa = fmaxf(fmaf(da * rs, s_fg2[j0], s_fbt2[j0]), 0.f);
    ab = fmaxf(fmaf(db * rs, s_fg2[j1], s_fbt2[j1]), 0.f);

    // output layer (64 -> 3), reduce across warp
    float n0 = wredall(fmaf(aa, s_fwo[j0 * 3 + 0], ab * s_fwo[j1 * 3 + 0]));
    float n1 = wredall(fmaf(aa, s_fwo[j0 * 3 + 1], ab * s_fwo[j1 * 3 + 1]));
    float n2 = wredall(fmaf(aa, s_fwo[j0 * 3 + 2], ab * s_fwo[j1 * 3 + 2]));
    if (lane == 0) {
        g_unu[3 * node + 0] = tau_i * (n0 + s_fbo[0]);
        g_unu[3 * node + 1] = tau_i * (n1 + s_fbo[1]);
        g_unu[3 * node + 2] = tau_i * (n2 + s_fbo[2]);
    }
}

// ---------------- flux divergence + hat_u, 2 nodes per warp ----------------
__global__ void k_flux(const float* __restrict__ tau) {
    int gt     = blockIdx.x * blockDim.x + threadIdx.x;
    int node   = gt >> 4;
    int lane16 = gt & 15;
    int s = g_rowptr[node], e = g_rowptr[node + 1];
    float s0 = 0.f, s1 = 0.f, s2 = 0.f;
    for (int p = s + lane16; p < e; p += 16) {
        int2 ed = g_edge[p];
        float w = __int_as_float(ed.y);
        int   c = ed.x;
        s0 = fmaf(w, __ldg(&g_unu[3 * c + 0]), s0);
        s1 = fmaf(w, __ldg(&g_unu[3 * c + 1]), s1);
        s2 = fmaf(w, __ldg(&g_unu[3 * c + 2]), s2);
    }
    s0 = hredall(s0); s1 = hredall(s1); s2 = hredall(s2);
    if (lane16 == 0) {
        float d  = g_deg[node];
        float d0 = d * g_unu[3 * node + 0] - s0;
        float d1 = d * g_unu[3 * node + 1] - s1;
        float d2 = d * g_unu[3 * node + 2] - s2;
        float ds = sqrtf(d0 * d0 + d1 * d1 + d2 * d2 + 1e-12f);
        g_hat[node] = tau[node] + DTC * (g_P[node] - ds);   // Q = 0
    }
}

// ---------------- GEMV1: acc1 += v[r]*mw1[r][:], float4 per thread ----------------
#define G1_ROWS 200
__global__ void k_gemv1(const float* __restrict__ mw1) {
    int c  = threadIdx.x;                  // 0..127 -> float4 column group
    int r0 = blockIdx.x * G1_ROWS;         // NN % G1_ROWS == 0 -> no straddling
    const float* v = (r0 < NN) ? (g_hat + r0) : (g_P + (r0 - NN));
    const float4* m4 = (const float4*)mw1 + (size_t)r0 * (MH / 4) + c;
    float4 acc = make_float4(0.f, 0.f, 0.f, 0.f);
#pragma unroll 8
    for (int i = 0; i < G1_ROWS; i++) {
        float  vv = __ldg(&v[i]);
        float4 m  = __ldg(&m4[(size_t)i * (MH / 4)]);
        acc.x = fmaf(vv, m.x, acc.x);
        acc.y = fmaf(vv, m.y, acc.y);
        acc.z = fmaf(vv, m.z, acc.z);
        acc.w = fmaf(vv, m.w, acc.w);
    }
    atomicAdd(&g_acc1[4 * c + 0], acc.x);
    atomicAdd(&g_acc1[4 * c + 1], acc.y);
    atomicAdd(&g_acc1[4 * c + 2], acc.z);
    atomicAdd(&g_acc1[4 * c + 3], acc.w);
}

// ---------------- LayerNorm(512) + relu -> hm ----------------
__global__ void k_ln(const float* __restrict__ mb1, const float* __restrict__ mg1,
                     const float* __restrict__ mbt1) {
    __shared__ float red[16];
    int tid = threadIdx.x;                 // 512
    float x = g_acc1[tid] + mb1[tid];
    float v = wredall(x);
    if ((tid & 31) == 0) red[tid >> 5] = v;
    __syncthreads();
    float m = 0.f;
#pragma unroll
    for (int i = 0; i < 16; i++) m += red[i];
    m *= (1.f / MH);
    __syncthreads();
    float d = x - m;
    float v2 = wredall(d * d);
    if ((tid & 31) == 0) red[tid >> 5] = v2;
    __syncthreads();
    float var = 0.f;
#pragma unroll
    for (int i = 0; i < 16; i++) var += red[i];
    var *= (1.f / MH);
    g_hm[tid] = fmaxf(fmaf(d * rsqrtf(var + EPSF), mg1[tid], mbt1[tid]), 0.f);
}

// ---------------- out init: out[n] = mbo[n] + tau[n] ----------------
__global__ void k_outinit(const float* __restrict__ mbo, const float* __restrict__ tau,
                          float* __restrict__ out) {
    int n = blockIdx.x * blockDim.x + threadIdx.x;
    if (n < NN) out[n] = mbo[n] + tau[n];
}

// ---------------- GEMV2: out[4c..] += sum_k hm[k]*mwo[k][4c..], float4, 2D grid ----------------
#define G2_KC 128                         // k-chunk per block.y (4 chunks)
__global__ void k_gemv2(const float* __restrict__ mwo, float* __restrict__ out) {
    __shared__ float s_hm[G2_KC];
    int tid = threadIdx.x;                 // 128
    int kc  = blockIdx.y * G2_KC;
    s_hm[tid] = g_hm[kc + tid];
    __syncthreads();
    int c4 = blockIdx.x * 128 + tid;       // float4 column group, 12500 total
    if (c4 >= NN / 4) return;
    const float4* w4 = (const float4*)mwo + (size_t)kc * (NN / 4) + c4;
    float4 acc = make_float4(0.f, 0.f, 0.f, 0.f);
#pragma unroll 8
    for (int kk = 0; kk < G2_KC; kk++) {
        float  h = s_hm[kk];
        float4 m = __ldg(&w4[(size_t)kk * (NN / 4)]);
        acc.x = fmaf(h, m.x, acc.x);
        acc.y = fmaf(h, m.y, acc.y);
        acc.z = fmaf(h, m.z, acc.z);
        acc.w = fmaf(h, m.w, acc.w);
    }
    atomicAdd(&out[4 * c4 + 0], acc.x);
    atomicAdd(&out[4 * c4 + 1], acc.y);
    atomicAdd(&out[4 * c4 + 2], acc.z);
    atomicAdd(&out[4 * c4 + 3], acc.w);
}

// ---------------- host orchestration ----------------
extern "C" void kernel_launch(void* const* d_in, const int* in_sizes, int n_in,
                              void* d_out, int out_size) {
    const float* tau   = (const float*)d_in[0];
    const int*   eidx  = (const int*)d_in[2];
    const float* ew    = (const float*)d_in[3];
    const float* gamma = (const float*)d_in[4];
    const float* lam   = (const float*)d_in[5];
    const float* fw1   = (const float*)d_in[7];
    const float* fb1   = (const float*)d_in[8];
    const float* fg1   = (const float*)d_in[9];
    const float* fbt1  = (const float*)d_in[10];
    const float* fw2   = (const float*)d_in[11];
    const float* fb2   = (const float*)d_in[12];
    const float* fg2   = (const float*)d_in[13];
    const float* fbt2  = (const float*)d_in[14];
    const float* fwo   = (const float*)d_in[15];
    const float* fbo   = (const float*)d_in[16];
    const float* mw1   = (const float*)d_in[17];
    const float* mb1   = (const float*)d_in[18];
    const float* mg1   = (const float*)d_in[19];
    const float* mbt1  = (const float*)d_in[20];
    const float* mwo   = (const float*)d_in[21];
    const float* mbo   = (const float*)d_in[22];
    float* out = (float*)d_out;

    // init + CSR build (deg precomputed in hist)
    k_init<<<(NN + 255) / 256, 256>>>(tau);
    k_hist<<<(NE / 4 + 255) / 256, 256>>>(eidx, ew);
    k_scan<<<1, 1024>>>();
    k_scatter<<<(NE / 4 + 255) / 256, 256>>>(eidx, ew);

    // Taylor loop: 2 nodes per warp -> NN/2 warps = 3125 blocks of 256
    float *pa = nullptr, *pb = nullptr;
    cudaGetSymbolAddress((void**)&pa, g_ta);
    cudaGetSymbolAddress((void**)&pb, g_tb);
    const int half_blocks = NN / 16;             // 3125 (16 threads per node)
    for (int k = 1; k <= KTE; k++) {
        float coef = -BDT / (float)k;
        k_spmv<<<half_blocks, 256>>>(pa, pb, coef);
        float* t = pa; pa = pb; pb = t;
    }

    // node MLP -> u_nu ; flux/div -> hat_u
    k_mlp<<<(NN + 31) / 32, 1024>>>(tau, gamma, lam, fw1, fb1, fg1, fbt1,
                                    fw2, fb2, fg2, fbt2, fwo, fbo);
    k_flux<<<half_blocks, 256>>>(tau);

    // big GEMVs + LN
    k_gemv1<<<(2 * NN) / G1_ROWS, 128>>>(mw1);   // 500 blocks
    k_ln<<<1, MH>>>(mb1, mg1, mbt1);
    k_outinit<<<(NN + 255) / 256, 256>>>(mbo, tau, out);
    {
        dim3 g((NN / 4 + 127) / 128, MH / G2_KC);  // (98, 4)
        k_gemv2<<<g, 128>>>(mwo, out);
    }
}